// round 9
// baseline (speedup 1.0000x reference)
#include <cuda_runtime.h>
#include <cuda_bf16.h>
#include <cstdint>

namespace {

// smem byte offsets (main kernel)
constexpr int OFF_AHI = 0;
constexpr int A_TILE  = 128 * 128;          // 128 rows x 128B (64 bf16)
constexpr int OFF_ALO = OFF_AHI + A_TILE;   // 16384
constexpr int OFF_BHI = OFF_ALO + A_TILE;   // 32768
constexpr int B_TILE  = 224 * 128;          // 28672
constexpr int OFF_BLO = OFF_BHI + B_TILE;   // 61440
constexpr int MAIN_BYTES = OFF_BLO + B_TILE;      // 90112
constexpr int EPI_BYTES  = 16 * 32 * 58 * 4;      // 118784
constexpr int SMEM_BYTES = EPI_BYTES;             // max(90112, 118784)

// scratch: [z2 = tensor*16 + b*2 + wp][h][u][c] bf16, c contiguous
__device__ __align__(16) __nv_bfloat16 g_hi[2ull * 16 * 64 * 32 * 256];
__device__ __align__(16) __nv_bfloat16 g_lo[2ull * 16 * 64 * 32 * 256];

__device__ __forceinline__ uint32_t smem_u32(const void* p) {
    uint32_t a;
    asm("{ .reg .u64 t; cvta.to.shared.u64 t, %1; cvt.u32.u64 %0, t; }" : "=r"(a) : "l"(p));
    return a;
}
__device__ __forceinline__ void ldsm_x4(uint32_t& r0, uint32_t& r1, uint32_t& r2, uint32_t& r3,
                                        uint32_t addr) {
    asm volatile("ldmatrix.sync.aligned.m8n8.x4.shared.b16 {%0,%1,%2,%3}, [%4];"
                 : "=r"(r0), "=r"(r1), "=r"(r2), "=r"(r3) : "r"(addr));
}
__device__ __forceinline__ void ldsm_x2(uint32_t& r0, uint32_t& r1, uint32_t addr) {
    asm volatile("ldmatrix.sync.aligned.m8n8.x2.shared.b16 {%0,%1}, [%2];"
                 : "=r"(r0), "=r"(r1) : "r"(addr));
}
__device__ __forceinline__ void mma_bf16(float* d, const uint32_t* a, const uint32_t* b) {
    asm volatile("mma.sync.aligned.m16n8k16.row.col.f32.bf16.bf16.f32 "
                 "{%0,%1,%2,%3}, {%4,%5,%6,%7}, {%8,%9}, {%0,%1,%2,%3};"
                 : "+f"(d[0]), "+f"(d[1]), "+f"(d[2]), "+f"(d[3])
                 : "r"(a[0]), "r"(a[1]), "r"(a[2]), "r"(a[3]), "r"(b[0]), "r"(b[1]));
}

// ---------------- conversion: fp32 [b][c][h][w] -> bf16 hi/lo [z2][h][u][c]
__global__ void __launch_bounds__(256)
convert_kernel(const float* __restrict__ in1, const float* __restrict__ in2)
{
    __shared__ float tile[32][65];
    const int cb = blockIdx.x;            // 0..7
    const int h  = blockIdx.y;            // 0..63
    const int z  = blockIdx.z;            // tensor*8 + b
    const float* src = (z < 8) ? in1 : in2;
    const int b = z & 7;
    const int t = threadIdx.x;

#pragma unroll
    for (int it = 0; it < 8; ++it) {
        int idx = t + 256 * it;
        int c = idx >> 6, w = idx & 63;
        tile[c][w] = src[(((size_t)b * 256 + cb * 32 + c) * 64 + h) * 64 + w];
    }
    __syncthreads();
#pragma unroll
    for (int it = 0; it < 8; ++it) {
        int idx = t + 256 * it;
        int row = idx >> 5, c = idx & 31;    // row = wp*32 + u
        int wp = row >> 5, u = row & 31;
        int w  = wp + 2 * u;
        float v = tile[c][w];
        __nv_bfloat16 hi = __float2bfloat16(v);
        __nv_bfloat16 lo = __float2bfloat16(v - __bfloat162float(hi));
        // z2 = tensor*16 + b*2 + wp
        int z2 = (z >> 3) * 16 + b * 2 + wp;
        size_t o = (((size_t)z2 * 64 + h) * 32 + u) * 256 + cb * 32 + c;
        g_hi[o] = hi;
        g_lo[o] = lo;
    }
}

// ---------------- main kernel: banded GEMM via mma.sync bf16 (3-term hi/lo)
__global__ void __launch_bounds__(512, 1)
corr_mma_kernel(float* __restrict__ out)
{
    extern __shared__ char smem[];
    const uint32_t sb = smem_u32(smem);
    const int tid  = threadIdx.x;
    const int lane = tid & 31;
    const int wq   = tid >> 5;        // 0..15
    const int wr   = wq & 3;          // k = wr
    const int wc   = wq >> 2;         // m = m0 + wc

    const int mq = blockIdx.x;        // 0..5
    const int g  = blockIdx.y;        // 0..15
    const int z  = blockIdx.z;        // b*2 + wp
    const int b  = z >> 1, wp = z & 1;
    const int pi = g & 1, ig = g >> 1;
    const int hbase = pi + 8 * ig;    // h_k = hbase + 2k
    const int m0 = mq * 4;

    const size_t SA = (size_t)(b * 2 + wp) * (64 * 32 * 256);
    const size_t SB = (size_t)(16 + b * 2 + wp) * (64 * 32 * 256);

    // ldmatrix per-lane address components
    const int l7 = lane & 7;
    const int lh = (lane >> 3) & 1;
    const int lq = lane >> 4;
    const uint32_t kxor = l7 << 4;
    const uint32_t khA  = lq * 16;
    const uint32_t khB  = lh * 16;
    uint32_t abase[2], bbase[3], bbase6;
#pragma unroll
    for (int mt = 0; mt < 2; ++mt) {
        int row = 32 * wr + 16 * mt + l7 + 8 * lh;
        abase[mt] = (row >> 3) * 1024 + l7 * 128;
    }
#pragma unroll
    for (int p = 0; p < 3; ++p) {
        int row = 56 * wc + 16 * p + 8 * lq + l7;
        bbase[p] = (row >> 3) * 1024 + l7 * 128;
    }
    {
        int row = 56 * wc + 48 + l7;
        bbase6 = (row >> 3) * 1024 + l7 * 128;
    }

    float acc[2][7][4];
#pragma unroll
    for (int mt = 0; mt < 2; ++mt)
#pragma unroll
        for (int nt = 0; nt < 7; ++nt)
#pragma unroll
            for (int r = 0; r < 4; ++r) acc[mt][nt][r] = 0.f;

    // staging thread mapping
    const int sr = tid >> 3;      // "row group" helper
    const int sq = tid & 7;       // 16B quad in 128B row

    for (int cc = 0; cc < 4; ++cc) {
        const int c0 = cc * 64;
        __syncthreads();
        // ---- stage A hi/lo: 128 rows x 8 quads = 1024 idx
#pragma unroll
        for (int it = 0; it < 2; ++it) {
            int idx = tid + 512 * it;
            int row = idx >> 3, q = idx & 7;
            int k = row >> 5, u = row & 31;
            int h = hbase + 2 * k;
            size_t so = SA + ((size_t)h * 32 + u) * 256 + c0 + q * 8;
            uint32_t dst = (row >> 3) * 1024 + (row & 7) * 128 + ((q * 16) ^ ((row & 7) << 4));
            *(float4*)(smem + OFF_AHI + dst) = *(const float4*)(g_hi + so);
            *(float4*)(smem + OFF_ALO + dst) = *(const float4*)(g_lo + so);
        }
        // ---- stage B hi/lo: 224 rows x 8 quads = 1792 idx (zero invalid)
#pragma unroll
        for (int it = 0; it < 4; ++it) {
            int idx = tid + 512 * it;
            if (idx < 1792) {
                int row = idx >> 3, q = idx & 7;
                int mloc = row / 56;
                int x = row - mloc * 56;
                int h2 = hbase - 20 + 2 * (m0 + mloc);
                bool val = (x >= 10) & (x < 42) & (h2 >= 0) & (h2 < 64);
                float4 vh = make_float4(0.f, 0.f, 0.f, 0.f), vl = vh;
                if (val) {
                    size_t so = SB + ((size_t)h2 * 32 + (x - 10)) * 256 + c0 + q * 8;
                    vh = *(const float4*)(g_hi + so);
                    vl = *(const float4*)(g_lo + so);
                }
                uint32_t dst = (row >> 3) * 1024 + (row & 7) * 128 + ((q * 16) ^ ((row & 7) << 4));
                *(float4*)(smem + OFF_BHI + dst) = vh;
                *(float4*)(smem + OFF_BLO + dst) = vl;
            }
        }
        __syncthreads();

        // ---- 3 terms x 4 k16-steps of mma
#pragma unroll
        for (int t3 = 0; t3 < 3; ++t3) {
            const uint32_t uA = sb + (t3 < 2 ? OFF_AHI : OFF_ALO);
            const uint32_t uB = sb + (t3 == 1 ? OFF_BLO : OFF_BHI);
#pragma unroll
            for (int s = 0; s < 4; ++s) {
                const uint32_t kb = 32 * s;
                uint32_t a[2][4];
#pragma unroll
                for (int mt = 0; mt < 2; ++mt)
                    ldsm_x4(a[mt][0], a[mt][1], a[mt][2], a[mt][3],
                            uA + abase[mt] + ((kb + khA) ^ kxor));
                uint32_t bf[7][2];
#pragma unroll
                for (int p = 0; p < 3; ++p)
                    ldsm_x4(bf[2 * p][0], bf[2 * p][1], bf[2 * p + 1][0], bf[2 * p + 1][1],
                            uB + bbase[p] + ((kb + khB) ^ kxor));
                ldsm_x2(bf[6][0], bf[6][1], uB + bbase6 + ((kb + khB) ^ kxor));
#pragma unroll
                for (int mt = 0; mt < 2; ++mt)
#pragma unroll
                    for (int nt = 0; nt < 7; ++nt)
                        mma_bf16(acc[mt][nt], a[mt], bf[nt]);
            }
        }
    }

    // ---- epilogue: per-warp smem [u:32][x:58], band gather, store
    __syncthreads();
    float* sD = (float*)(smem + wq * (32 * 58 * 4));
#pragma unroll
    for (int mt = 0; mt < 2; ++mt)
#pragma unroll
        for (int nt = 0; nt < 7; ++nt)
#pragma unroll
            for (int r = 0; r < 4; ++r) {
                int u = 16 * mt + (lane >> 2) + 8 * (r >> 1);
                int x = 8 * nt + 2 * (lane & 3) + (r & 1);
                sD[u * 58 + x] = acc[mt][nt][r];
            }
    __syncwarp();

    const int dy = m0 + wc - wr;
    if (dy >= 0 && dy < 21) {
        const int hk = hbase + 2 * wr;
        const float scale = 1.0f / 256.0f;
        size_t ob = ((size_t)b * 441 + (size_t)dy * 21) * 4096 + (size_t)hk * 64 + wp + 2 * lane;
        const float* sr0 = sD + lane * 58 + lane;
#pragma unroll
        for (int j = 0; j < 21; ++j)
            out[ob + (size_t)j * 4096] = sr0[j] * scale;
    }
}

} // namespace

extern "C" void kernel_launch(void* const* d_in, const int* in_sizes, int n_in,
                              void* d_out, int out_size)
{
    const float* in1 = (const float*)d_in[0];
    const float* in2 = (const float*)d_in[1];
    float* out = (float*)d_out;

    cudaFuncSetAttribute(corr_mma_kernel,
                         cudaFuncAttributeMaxDynamicSharedMemorySize, SMEM_BYTES);

    dim3 cgrid(8, 64, 16);
    convert_kernel<<<cgrid, 256>>>(in1, in2);

    dim3 grid(6, 16, 16);
    corr_mma_kernel<<<grid, 512, SMEM_BYTES>>>(out);
}

// round 10
// speedup vs baseline: 2.2338x; 2.2338x over previous
#include <cuda_runtime.h>
#include <cuda_fp16.h>
#include <cstdint>

namespace {

// double-buffered smem layout (byte offsets within one buffer)
constexpr int OFF_AHI = 0;
constexpr int A_TILE  = 128 * 128;            // 128 rows x 128B (64 fp16)
constexpr int OFF_ALO = OFF_AHI + A_TILE;     // 16384
constexpr int OFF_B   = OFF_ALO + A_TILE;     // 32768
constexpr int B_TILE  = 224 * 128;            // 28672
constexpr int BUF     = OFF_B + B_TILE;       // 61440 per buffer
constexpr int EPI_BYTES = 16 * 32 * 58 * 4;   // 118784
constexpr int SMEM_BYTES = 2 * BUF;           // 122880 >= EPI_BYTES

// scratch: g_hi [z2 = tensor*16 + b*2 + wp][h][u][c] fp16 (both tensors)
//          g_lo same layout, tensor-0 (input1) only
__device__ __align__(16) __half g_hi[2ull * 16 * 64 * 32 * 256];
__device__ __align__(16) __half g_lo[1ull * 16 * 64 * 32 * 256];

__device__ __forceinline__ uint32_t smem_u32(const void* p) {
    uint32_t a;
    asm("{ .reg .u64 t; cvta.to.shared.u64 t, %1; cvt.u32.u64 %0, t; }" : "=r"(a) : "l"(p));
    return a;
}
__device__ __forceinline__ void ldsm_x4(uint32_t& r0, uint32_t& r1, uint32_t& r2, uint32_t& r3,
                                        uint32_t addr) {
    asm volatile("ldmatrix.sync.aligned.m8n8.x4.shared.b16 {%0,%1,%2,%3}, [%4];"
                 : "=r"(r0), "=r"(r1), "=r"(r2), "=r"(r3) : "r"(addr));
}
__device__ __forceinline__ void ldsm_x2(uint32_t& r0, uint32_t& r1, uint32_t addr) {
    asm volatile("ldmatrix.sync.aligned.m8n8.x2.shared.b16 {%0,%1}, [%2];"
                 : "=r"(r0), "=r"(r1) : "r"(addr));
}
__device__ __forceinline__ void mma_f16(float* d, const uint32_t* a, const uint32_t* b) {
    asm volatile("mma.sync.aligned.m16n8k16.row.col.f32.f16.f16.f32 "
                 "{%0,%1,%2,%3}, {%4,%5,%6,%7}, {%8,%9}, {%0,%1,%2,%3};"
                 : "+f"(d[0]), "+f"(d[1]), "+f"(d[2]), "+f"(d[3])
                 : "r"(a[0]), "r"(a[1]), "r"(a[2]), "r"(a[3]), "r"(b[0]), "r"(b[1]));
}
__device__ __forceinline__ void cp16(uint32_t dst, const void* src) {
    asm volatile("cp.async.ca.shared.global [%0], [%1], 16;" :: "r"(dst), "l"(src));
}

// ---------------- conversion: fp32 [b][c][h][w] -> fp16 (hi[,lo]) [z2][h][u][c]
__global__ void __launch_bounds__(256)
convert_kernel(const float* __restrict__ in1, const float* __restrict__ in2)
{
    __shared__ float tile[32][65];
    const int cb = blockIdx.x;            // 0..7
    const int h  = blockIdx.y;            // 0..63
    const int z  = blockIdx.z;            // tensor*8 + b
    const float* src = (z < 8) ? in1 : in2;
    const int b = z & 7;
    const int t = threadIdx.x;

#pragma unroll
    for (int it = 0; it < 8; ++it) {
        int idx = t + 256 * it;
        int c = idx >> 6, w = idx & 63;
        tile[c][w] = src[(((size_t)b * 256 + cb * 32 + c) * 64 + h) * 64 + w];
    }
    __syncthreads();
#pragma unroll
    for (int it = 0; it < 8; ++it) {
        int idx = t + 256 * it;
        int row = idx >> 5, c = idx & 31;    // row = wp*32 + u
        int wp = row >> 5, u = row & 31;
        int w  = wp + 2 * u;
        float v = tile[c][w];
        __half hi = __float2half(v);
        int z2 = (z >> 3) * 16 + b * 2 + wp;
        size_t o = (((size_t)z2 * 64 + h) * 32 + u) * 256 + cb * 32 + c;
        g_hi[o] = hi;
        if (z < 8) {
            size_t ol = (((size_t)(b * 2 + wp) * 64 + h) * 32 + u) * 256 + cb * 32 + c;
            g_lo[ol] = __float2half(v - __half2float(hi));
        }
    }
}

// ---------------- main: banded GEMM, fp16 2-term, cp.async double-buffered
__global__ void __launch_bounds__(512, 1)
corr_mma_kernel(float* __restrict__ out)
{
    extern __shared__ char smem[];
    const uint32_t sb = smem_u32(smem);
    const int tid  = threadIdx.x;
    const int lane = tid & 31;
    const int wq   = tid >> 5;        // 0..15
    const int wr   = wq & 3;          // k = wr
    const int wc   = wq >> 2;         // m = m0 + wc

    const int mq = blockIdx.x;        // 0..5
    const int g  = blockIdx.y;        // 0..15
    const int z  = blockIdx.z;        // b*2 + wp
    const int b  = z >> 1, wp = z & 1;
    const int pi = g & 1, ig = g >> 1;
    const int hbase = pi + 8 * ig;    // h_k = hbase + 2k
    const int m0 = mq * 4;

    const size_t SA = (size_t)(b * 2 + wp) * (64 * 32 * 256);           // g_hi / g_lo (tensor0)
    const size_t SB = (size_t)(16 + b * 2 + wp) * (64 * 32 * 256);      // g_hi (tensor1)

    // ldmatrix per-lane address components (same layout as validated round 9)
    const int l7 = lane & 7;
    const int lh = (lane >> 3) & 1;
    const int lq = lane >> 4;
    const uint32_t kxor = l7 << 4;
    const uint32_t khA  = lq * 16;
    const uint32_t khB  = lh * 16;
    uint32_t abase[2], bbase[3], bbase6;
#pragma unroll
    for (int mt = 0; mt < 2; ++mt) {
        int row = 32 * wr + 16 * mt + l7 + 8 * lh;
        abase[mt] = (row >> 3) * 1024 + l7 * 128;
    }
#pragma unroll
    for (int p = 0; p < 3; ++p) {
        int row = 56 * wc + 16 * p + 8 * lq + l7;
        bbase[p] = (row >> 3) * 1024 + l7 * 128;
    }
    {
        int row = 56 * wc + 48 + l7;
        bbase6 = (row >> 3) * 1024 + l7 * 128;
    }

    float acc[2][5][4];                // [mt][window w -> nt = w + 2*mt]
#pragma unroll
    for (int mt = 0; mt < 2; ++mt)
#pragma unroll
        for (int w = 0; w < 5; ++w)
#pragma unroll
            for (int r = 0; r < 4; ++r) acc[mt][w][r] = 0.f;

    // ---- zero B pad/OOB rows in both buffers once (row set is chunk-invariant)
    {
        float4 zz = make_float4(0.f, 0.f, 0.f, 0.f);
        for (int idx = tid; idx < 2 * 224 * 8; idx += 512) {
            int bi = idx >= 224 * 8;
            int k2 = idx - bi * 224 * 8;
            int row = k2 >> 3, q = k2 & 7;
            uint32_t dst = (row >> 3) * 1024 + (row & 7) * 128 + ((q * 16) ^ ((row & 7) << 4));
            *(float4*)(smem + bi * BUF + OFF_B + dst) = zz;
        }
    }
    __syncthreads();

    // staging lambda-ish macro via explicit code: chunk cc -> buffer bsel
    auto stage = [&](int cc, int bsel) {
        const int c0 = cc * 64;
        const uint32_t bb = sb + bsel * BUF;
        // A hi/lo: 128 rows x 8 quads
#pragma unroll
        for (int it = 0; it < 2; ++it) {
            int idx = tid + 512 * it;
            int row = idx >> 3, q = idx & 7;
            int k = row >> 5, u = row & 31;
            int h = hbase + 2 * k;
            size_t so = SA + ((size_t)h * 32 + u) * 256 + c0 + q * 8;
            uint32_t dst = (row >> 3) * 1024 + (row & 7) * 128 + ((q * 16) ^ ((row & 7) << 4));
            cp16(bb + OFF_AHI + dst, g_hi + so);
            cp16(bb + OFF_ALO + dst, g_lo + so);
        }
        // B: 128 valid rows (x in [10,42)) x 8 quads; skip OOB h2 (stay zero)
#pragma unroll
        for (int it = 0; it < 2; ++it) {
            int idx = tid + 512 * it;
            int vr = idx >> 3, q = idx & 7;
            int mloc = vr >> 5, xv = vr & 31;
            int h2 = hbase - 20 + 2 * (m0 + mloc);
            if (h2 >= 0 && h2 < 64) {
                int row = mloc * 56 + xv + 10;
                size_t so = SB + ((size_t)h2 * 32 + xv) * 256 + c0 + q * 8;
                uint32_t dst = (row >> 3) * 1024 + (row & 7) * 128 + ((q * 16) ^ ((row & 7) << 4));
                cp16(bb + OFF_B + dst, g_hi + so);
            }
        }
        asm volatile("cp.async.commit_group;");
    };

    stage(0, 0);

    for (int cc = 0; cc < 4; ++cc) {
        if (cc < 3) {
            stage(cc + 1, (cc + 1) & 1);
            asm volatile("cp.async.wait_group 1;");
        } else {
            asm volatile("cp.async.wait_group 0;");
        }
        __syncthreads();

        const uint32_t bufb = sb + (cc & 1) * BUF;
        const uint32_t uAhi = bufb + OFF_AHI;
        const uint32_t uAlo = bufb + OFF_ALO;
        const uint32_t uB   = bufb + OFF_B;
#pragma unroll
        for (int s = 0; s < 4; ++s) {
            const uint32_t kb = 32 * s;
            uint32_t ah[2][4], al[2][4];
#pragma unroll
            for (int mt = 0; mt < 2; ++mt) {
                ldsm_x4(ah[mt][0], ah[mt][1], ah[mt][2], ah[mt][3],
                        uAhi + abase[mt] + ((kb + khA) ^ kxor));
                ldsm_x4(al[mt][0], al[mt][1], al[mt][2], al[mt][3],
                        uAlo + abase[mt] + ((kb + khA) ^ kxor));
            }
            uint32_t bf[7][2];
#pragma unroll
            for (int p = 0; p < 3; ++p)
                ldsm_x4(bf[2 * p][0], bf[2 * p][1], bf[2 * p + 1][0], bf[2 * p + 1][1],
                        uB + bbase[p] + ((kb + khB) ^ kxor));
            ldsm_x2(bf[6][0], bf[6][1], uB + bbase6 + ((kb + khB) ^ kxor));
#pragma unroll
            for (int mt = 0; mt < 2; ++mt)
#pragma unroll
                for (int w = 0; w < 5; ++w) {
                    const int nt = w + 2 * mt;
                    mma_f16(acc[mt][w], ah[mt], bf[nt]);
                    mma_f16(acc[mt][w], al[mt], bf[nt]);
                }
        }
        __syncthreads();
    }

    // ---- epilogue: per-warp smem [u:32][x:58], band gather, store
    float* sD = (float*)(smem + wq * (32 * 58 * 4));
#pragma unroll
    for (int mt = 0; mt < 2; ++mt)
#pragma unroll
        for (int w = 0; w < 5; ++w) {
            const int nt = w + 2 * mt;
#pragma unroll
            for (int r = 0; r < 4; ++r) {
                int u = 16 * mt + (lane >> 2) + 8 * (r >> 1);
                int x = 8 * nt + 2 * (lane & 3) + (r & 1);
                sD[u * 58 + x] = acc[mt][w][r];
            }
        }
    __syncwarp();

    const int dy = m0 + wc - wr;
    if (dy >= 0 && dy < 21) {
        const int hk = hbase + 2 * wr;
        const float scale = 1.0f / 256.0f;
        size_t ob = ((size_t)b * 441 + (size_t)dy * 21) * 4096 + (size_t)hk * 64 + wp + 2 * lane;
        const float* sr0 = sD + lane * 58 + lane;
#pragma unroll
        for (int j = 0; j < 21; ++j)
            out[ob + (size_t)j * 4096] = sr0[j] * scale;
    }
}

} // namespace

extern "C" void kernel_launch(void* const* d_in, const int* in_sizes, int n_in,
                              void* d_out, int out_size)
{
    const float* in1 = (const float*)d_in[0];
    const float* in2 = (const float*)d_in[1];
    float* out = (float*)d_out;

    cudaFuncSetAttribute(corr_mma_kernel,
                         cudaFuncAttributeMaxDynamicSharedMemorySize, SMEM_BYTES);

    dim3 cgrid(8, 64, 16);
    convert_kernel<<<cgrid, 256>>>(in1, in2);

    dim3 grid(6, 16, 16);
    corr_mma_kernel<<<grid, 512, SMEM_BYTES>>>(out);
}

// round 11
// speedup vs baseline: 4.4890x; 2.0095x over previous
#include <cuda_runtime.h>
#include <cuda_fp16.h>
#include <cstdint>

namespace {

// double-buffered smem layout (byte offsets within one buffer)
constexpr int OFF_A  = 0;
constexpr int A_TILE = 128 * 128;             // 128 rows x 128B (64 fp16)
constexpr int OFF_B  = OFF_A + A_TILE;        // 16384
constexpr int B_TILE = 224 * 128;             // 28672
constexpr int BUF    = OFF_B + B_TILE;        // 45056 per buffer
constexpr int EPI_BYTES  = 16 * 32 * 58 * 4;  // 118784
constexpr int SMEM_BYTES = EPI_BYTES;         // max(2*BUF=90112, 118784)

// scratch: [z2 = tensor*16 + b*2 + wp][h][u][c] fp16
__device__ __align__(16) __half g_hi[2ull * 16 * 64 * 32 * 256];

__device__ __forceinline__ uint32_t smem_u32(const void* p) {
    uint32_t a;
    asm("{ .reg .u64 t; cvta.to.shared.u64 t, %1; cvt.u32.u64 %0, t; }" : "=r"(a) : "l"(p));
    return a;
}
__device__ __forceinline__ void ldsm_x4(uint32_t& r0, uint32_t& r1, uint32_t& r2, uint32_t& r3,
                                        uint32_t addr) {
    asm volatile("ldmatrix.sync.aligned.m8n8.x4.shared.b16 {%0,%1,%2,%3}, [%4];"
                 : "=r"(r0), "=r"(r1), "=r"(r2), "=r"(r3) : "r"(addr));
}
__device__ __forceinline__ void ldsm_x2(uint32_t& r0, uint32_t& r1, uint32_t addr) {
    asm volatile("ldmatrix.sync.aligned.m8n8.x2.shared.b16 {%0,%1}, [%2];"
                 : "=r"(r0), "=r"(r1) : "r"(addr));
}
__device__ __forceinline__ void mma_f16(float* d, const uint32_t* a, const uint32_t* b) {
    asm volatile("mma.sync.aligned.m16n8k16.row.col.f32.f16.f16.f32 "
                 "{%0,%1,%2,%3}, {%4,%5,%6,%7}, {%8,%9}, {%0,%1,%2,%3};"
                 : "+f"(d[0]), "+f"(d[1]), "+f"(d[2]), "+f"(d[3])
                 : "r"(a[0]), "r"(a[1]), "r"(a[2]), "r"(a[3]), "r"(b[0]), "r"(b[1]));
}
__device__ __forceinline__ void cp16(uint32_t dst, const void* src) {
    asm volatile("cp.async.ca.shared.global [%0], [%1], 16;" :: "r"(dst), "l"(src));
}

// ---------------- conversion: fp32 [b][c][h][w] -> fp16 [z2][h][u][c]
__global__ void __launch_bounds__(256)
convert_kernel(const float* __restrict__ in1, const float* __restrict__ in2)
{
    __shared__ float tile[32][65];
    const int cb = blockIdx.x;            // 0..7
    const int h  = blockIdx.y;            // 0..63
    const int z  = blockIdx.z;            // tensor*8 + b
    const float* src = (z < 8) ? in1 : in2;
    const int b = z & 7;
    const int t = threadIdx.x;

#pragma unroll
    for (int it = 0; it < 8; ++it) {
        int idx = t + 256 * it;
        int c = idx >> 6, w = idx & 63;
        tile[c][w] = src[(((size_t)b * 256 + cb * 32 + c) * 64 + h) * 64 + w];
    }
    __syncthreads();
#pragma unroll
    for (int it = 0; it < 8; ++it) {
        int idx = t + 256 * it;
        int row = idx >> 5, c = idx & 31;    // row = wp*32 + u
        int wp = row >> 5, u = row & 31;
        int w  = wp + 2 * u;
        int z2 = (z >> 3) * 16 + b * 2 + wp;
        size_t o = (((size_t)z2 * 64 + h) * 32 + u) * 256 + cb * 32 + c;
        g_hi[o] = __float2half(tile[c][w]);
    }
}

// ---------------- main: banded GEMM, single fp16 term, cp.async double-buffered
__global__ void __launch_bounds__(512, 1)
corr_mma_kernel(float* __restrict__ out)
{
    extern __shared__ char smem[];
    const uint32_t sb = smem_u32(smem);
    const int tid  = threadIdx.x;
    const int lane = tid & 31;
    const int wq   = tid >> 5;        // 0..15
    const int wr   = wq & 3;          // k = wr
    const int wc   = wq >> 2;         // m = m0 + wc

    const int mq = blockIdx.x;        // 0..5
    const int g  = blockIdx.y;        // 0..15
    const int z  = blockIdx.z;        // b*2 + wp
    const int b  = z >> 1, wp = z & 1;
    const int pi = g & 1, ig = g >> 1;
    const int hbase = pi + 8 * ig;    // h_k = hbase + 2k
    const int m0 = mq * 4;

    const int dy = m0 + wc - wr;
    const bool dyvalid = (dy >= 0) & (dy < 21);

    const size_t SA = (size_t)(b * 2 + wp) * (64 * 32 * 256);
    const size_t SB = (size_t)(16 + b * 2 + wp) * (64 * 32 * 256);

    // ldmatrix per-lane address components
    const int l7 = lane & 7;
    const int lh = (lane >> 3) & 1;
    const int lq = lane >> 4;
    const uint32_t kxor = l7 << 4;
    const uint32_t khA  = lq * 16;
    const uint32_t khB  = lh * 16;
    uint32_t abase[2], bbase[3], bbase6;
#pragma unroll
    for (int mt = 0; mt < 2; ++mt) {
        int row = 32 * wr + 16 * mt + l7 + 8 * lh;
        abase[mt] = (row >> 3) * 1024 + l7 * 128;
    }
#pragma unroll
    for (int p = 0; p < 3; ++p) {
        int row = 56 * wc + 16 * p + 8 * lq + l7;
        bbase[p] = (row >> 3) * 1024 + l7 * 128;
    }
    {
        int row = 56 * wc + 48 + l7;
        bbase6 = (row >> 3) * 1024 + l7 * 128;
    }

    float acc[2][5][4];                // [mt][window w -> nt = w + 2*mt]
#pragma unroll
    for (int mt = 0; mt < 2; ++mt)
#pragma unroll
        for (int w = 0; w < 5; ++w)
#pragma unroll
            for (int r = 0; r < 4; ++r) acc[mt][w][r] = 0.f;

    // ---- zero B pad/OOB rows in both buffers once (row set is chunk-invariant)
    {
        float4 zz = make_float4(0.f, 0.f, 0.f, 0.f);
        for (int idx = tid; idx < 2 * 224 * 8; idx += 512) {
            int bi = idx >= 224 * 8;
            int k2 = idx - bi * 224 * 8;
            int row = k2 >> 3, q = k2 & 7;
            uint32_t dst = (row >> 3) * 1024 + (row & 7) * 128 + ((q * 16) ^ ((row & 7) << 4));
            *(float4*)(smem + bi * BUF + OFF_B + dst) = zz;
        }
    }
    __syncthreads();

    auto stage = [&](int cc, int bsel) {
        const int c0 = cc * 64;
        const uint32_t bb = sb + bsel * BUF;
        // A: 128 rows x 8 quads = 1024 cp.async over 512 threads
#pragma unroll
        for (int it = 0; it < 2; ++it) {
            int idx = tid + 512 * it;
            int row = idx >> 3, q = idx & 7;
            int k = row >> 5, u = row & 31;
            int h = hbase + 2 * k;
            size_t so = SA + ((size_t)h * 32 + u) * 256 + c0 + q * 8;
            uint32_t dst = (row >> 3) * 1024 + (row & 7) * 128 + ((q * 16) ^ ((row & 7) << 4));
            cp16(bb + OFF_A + dst, g_hi + so);
        }
        // B: 128 valid rows (x in [10,42)) x 8 quads; OOB h2 rows stay zero
#pragma unroll
        for (int it = 0; it < 2; ++it) {
            int idx = tid + 512 * it;
            int vr = idx >> 3, q = idx & 7;
            int mloc = vr >> 5, xv = vr & 31;
            int h2 = hbase - 20 + 2 * (m0 + mloc);
            if (h2 >= 0 && h2 < 64) {
                int row = mloc * 56 + xv + 10;
                size_t so = SB + ((size_t)h2 * 32 + xv) * 256 + c0 + q * 8;
                uint32_t dst = (row >> 3) * 1024 + (row & 7) * 128 + ((q * 16) ^ ((row & 7) << 4));
                cp16(bb + OFF_B + dst, g_hi + so);
            }
        }
        asm volatile("cp.async.commit_group;");
    };

    stage(0, 0);

    for (int cc = 0; cc < 4; ++cc) {
        if (cc < 3) {
            stage(cc + 1, (cc + 1) & 1);
            asm volatile("cp.async.wait_group 1;");
        } else {
            asm volatile("cp.async.wait_group 0;");
        }
        __syncthreads();

        if (dyvalid) {
            const uint32_t bufb = sb + (cc & 1) * BUF;
            const uint32_t uA = bufb + OFF_A;
            const uint32_t uB = bufb + OFF_B;
#pragma unroll
            for (int s = 0; s < 4; ++s) {
                const uint32_t kb = 32 * s;
                uint32_t ah[2][4];
#pragma unroll
                for (int mt = 0; mt < 2; ++mt)
                    ldsm_x4(ah[mt][0], ah[mt][1], ah[mt][2], ah[mt][3],
                            uA + abase[mt] + ((kb + khA) ^ kxor));
                uint32_t bf[7][2];
#pragma unroll
                for (int p = 0; p < 3; ++p)
                    ldsm_x4(bf[2 * p][0], bf[2 * p][1], bf[2 * p + 1][0], bf[2 * p + 1][1],
                            uB + bbase[p] + ((kb + khB) ^ kxor));
                ldsm_x2(bf[6][0], bf[6][1], uB + bbase6 + ((kb + khB) ^ kxor));
#pragma unroll
                for (int mt = 0; mt < 2; ++mt)
#pragma unroll
                    for (int w = 0; w < 5; ++w)
                        mma_f16(acc[mt][w], ah[mt], bf[w + 2 * mt]);
            }
        }
        __syncthreads();
    }

    // ---- epilogue: per-warp smem [u:32][x:58], band gather, store
    if (dyvalid) {
        float* sD = (float*)(smem + wq * (32 * 58 * 4));
#pragma unroll
        for (int mt = 0; mt < 2; ++mt)
#pragma unroll
            for (int w = 0; w < 5; ++w) {
                const int nt = w + 2 * mt;
#pragma unroll
                for (int r = 0; r < 4; ++r) {
                    int u = 16 * mt + (lane >> 2) + 8 * (r >> 1);
                    int x = 8 * nt + 2 * (lane & 3) + (r & 1);
                    sD[u * 58 + x] = acc[mt][w][r];
                }
            }
        __syncwarp();

        const int hk = hbase + 2 * wr;
        const float scale = 1.0f / 256.0f;
        size_t ob = ((size_t)b * 441 + (size_t)dy * 21) * 4096 + (size_t)hk * 64 + wp + 2 * lane;
        const float* sr0 = sD + lane * 58 + lane;
#pragma unroll
        for (int j = 0; j < 21; ++j)
            out[ob + (size_t)j * 4096] = sr0[j] * scale;
    }
}

} // namespace

extern "C" void kernel_launch(void* const* d_in, const int* in_sizes, int n_in,
                              void* d_out, int out_size)
{
    const float* in1 = (const float*)d_in[0];
    const float* in2 = (const float*)d_in[1];
    float* out = (float*)d_out;

    cudaFuncSetAttribute(corr_mma_kernel,
                         cudaFuncAttributeMaxDynamicSharedMemorySize, SMEM_BYTES);

    dim3 cgrid(8, 64, 16);
    convert_kernel<<<cgrid, 256>>>(in1, in2);

    dim3 grid(6, 16, 16);
    corr_mma_kernel<<<grid, 512, SMEM_BYTES>>>(out);
}

// round 12
// speedup vs baseline: 5.0157x; 1.1173x over previous
#include <cuda_runtime.h>
#include <cuda_fp16.h>
#include <cstdint>

namespace {

// double-buffered smem layout (byte offsets within one buffer)
constexpr int OFF_A  = 0;
constexpr int A_TILE = 128 * 128;             // 128 rows x 128B (64 fp16)
constexpr int OFF_B  = OFF_A + A_TILE;        // 16384
constexpr int B_TILE = 112 * 128;             // 14336 (2 m x 56 x)
constexpr int BUF    = OFF_B + B_TILE;        // 30720 per buffer
constexpr int EPI_BYTES  = 8 * 32 * 58 * 4;   // 59392
constexpr int SMEM_BYTES = 2 * BUF;           // 61440 >= EPI_BYTES

// scratch: [z2 = tensor*16 + b*2 + wp][h][u][c] fp16
__device__ __align__(16) __half g_hi[2ull * 16 * 64 * 32 * 256];

__device__ __forceinline__ uint32_t smem_u32(const void* p) {
    uint32_t a;
    asm("{ .reg .u64 t; cvta.to.shared.u64 t, %1; cvt.u32.u64 %0, t; }" : "=r"(a) : "l"(p));
    return a;
}
__device__ __forceinline__ void ldsm_x4(uint32_t& r0, uint32_t& r1, uint32_t& r2, uint32_t& r3,
                                        uint32_t addr) {
    asm volatile("ldmatrix.sync.aligned.m8n8.x4.shared.b16 {%0,%1,%2,%3}, [%4];"
                 : "=r"(r0), "=r"(r1), "=r"(r2), "=r"(r3) : "r"(addr));
}
__device__ __forceinline__ void ldsm_x2(uint32_t& r0, uint32_t& r1, uint32_t addr) {
    asm volatile("ldmatrix.sync.aligned.m8n8.x2.shared.b16 {%0,%1}, [%2];"
                 : "=r"(r0), "=r"(r1) : "r"(addr));
}
__device__ __forceinline__ void mma_f16(float* d, const uint32_t* a, const uint32_t* b) {
    asm volatile("mma.sync.aligned.m16n8k16.row.col.f32.f16.f16.f32 "
                 "{%0,%1,%2,%3}, {%4,%5,%6,%7}, {%8,%9}, {%0,%1,%2,%3};"
                 : "+f"(d[0]), "+f"(d[1]), "+f"(d[2]), "+f"(d[3])
                 : "r"(a[0]), "r"(a[1]), "r"(a[2]), "r"(a[3]), "r"(b[0]), "r"(b[1]));
}
__device__ __forceinline__ void cp16(uint32_t dst, const void* src) {
    asm volatile("cp.async.ca.shared.global [%0], [%1], 16;" :: "r"(dst), "l"(src));
}

// ---------------- conversion: fp32 [b][c][h][w] -> fp16 [z2][h][u][c]
__global__ void __launch_bounds__(256)
convert_kernel(const float* __restrict__ in1, const float* __restrict__ in2)
{
    __shared__ float tile[32][65];
    const int cb = blockIdx.x;            // 0..7
    const int h  = blockIdx.y;            // 0..63
    const int z  = blockIdx.z;            // tensor*8 + b
    const float* src = (z < 8) ? in1 : in2;
    const int b = z & 7;
    const int t = threadIdx.x;

#pragma unroll
    for (int it = 0; it < 8; ++it) {
        int idx = t + 256 * it;
        int c = idx >> 6, w = idx & 63;
        tile[c][w] = src[(((size_t)b * 256 + cb * 32 + c) * 64 + h) * 64 + w];
    }
    __syncthreads();
#pragma unroll
    for (int it = 0; it < 8; ++it) {
        int idx = t + 256 * it;
        int row = idx >> 5, c = idx & 31;    // row = wp*32 + u
        int wp = row >> 5, u = row & 31;
        int w  = wp + 2 * u;
        int z2 = (z >> 3) * 16 + b * 2 + wp;
        size_t o = (((size_t)z2 * 64 + h) * 32 + u) * 256 + cb * 32 + c;
        g_hi[o] = __float2half(tile[c][w]);
    }
}

// ---------------- main: banded GEMM, fp16 mma.sync, 256 thr, 2 CTAs/SM
__global__ void __launch_bounds__(256, 2)
corr_mma_kernel(float* __restrict__ out)
{
    extern __shared__ char smem[];
    const uint32_t sb = smem_u32(smem);
    const int tid  = threadIdx.x;
    const int lane = tid & 31;
    const int wq   = tid >> 5;        // 0..7
    const int wr   = wq & 3;          // k = wr
    const int wc   = wq >> 2;         // m = m0 + wc (0..1)

    const int mq = blockIdx.x;        // 0..11
    const int g  = blockIdx.y;        // 0..15
    const int z  = blockIdx.z;        // b*2 + wp
    const int b  = z >> 1, wp = z & 1;
    const int pi = g & 1, ig = g >> 1;
    const int hbase = pi + 8 * ig;    // h_k = hbase + 2k
    const int m0 = mq * 2;

    const int dy = m0 + wc - wr;
    const bool dyvalid = (dy >= 0) & (dy < 21);

    const size_t SA = (size_t)(b * 2 + wp) * (64 * 32 * 256);
    const size_t SB = (size_t)(16 + b * 2 + wp) * (64 * 32 * 256);

    // ldmatrix per-lane address components
    const int l7 = lane & 7;
    const int lh = (lane >> 3) & 1;
    const int lq = lane >> 4;
    const uint32_t kxor = l7 << 4;
    const uint32_t khA  = lq * 16;
    const uint32_t khB  = lh * 16;
    uint32_t abase[2], bbase[3], bbase6;
#pragma unroll
    for (int mt = 0; mt < 2; ++mt) {
        int row = 32 * wr + 16 * mt + l7 + 8 * lh;
        abase[mt] = (row >> 3) * 1024 + l7 * 128;
    }
#pragma unroll
    for (int p = 0; p < 3; ++p) {
        int row = 56 * wc + 16 * p + 8 * lq + l7;
        bbase[p] = (row >> 3) * 1024 + l7 * 128;
    }
    {
        int row = 56 * wc + 48 + l7;
        bbase6 = (row >> 3) * 1024 + l7 * 128;
    }

    float acc[2][5][4];                // [mt][window w -> nt = w + 2*mt]
#pragma unroll
    for (int mt = 0; mt < 2; ++mt)
#pragma unroll
        for (int w = 0; w < 5; ++w)
#pragma unroll
            for (int r = 0; r < 4; ++r) acc[mt][w][r] = 0.f;

    // ---- zero B pad/OOB rows in both buffers once (row set is chunk-invariant)
    {
        float4 zz = make_float4(0.f, 0.f, 0.f, 0.f);
        for (int idx = tid; idx < 2 * 112 * 8; idx += 256) {
            int bi = idx >= 112 * 8;
            int k2 = idx - bi * 112 * 8;
            int row = k2 >> 3, q = k2 & 7;
            uint32_t dst = (row >> 3) * 1024 + (row & 7) * 128 + ((q * 16) ^ ((row & 7) << 4));
            *(float4*)(smem + bi * BUF + OFF_B + dst) = zz;
        }
    }
    __syncthreads();

    auto stage = [&](int cc, int bsel) {
        const int c0 = cc * 64;
        const uint32_t bb = sb + bsel * BUF;
        // A: 128 rows x 8 quads = 1024 cp.async over 256 threads
#pragma unroll
        for (int it = 0; it < 4; ++it) {
            int idx = tid + 256 * it;
            int row = idx >> 3, q = idx & 7;
            int k = row >> 5, u = row & 31;
            int h = hbase + 2 * k;
            size_t so = SA + ((size_t)h * 32 + u) * 256 + c0 + q * 8;
            uint32_t dst = (row >> 3) * 1024 + (row & 7) * 128 + ((q * 16) ^ ((row & 7) << 4));
            cp16(bb + OFF_A + dst, g_hi + so);
        }
        // B: 64 valid rows (2 m x 32 xv) x 8 quads; OOB h2 rows stay zero
#pragma unroll
        for (int it = 0; it < 2; ++it) {
            int idx = tid + 256 * it;
            int vr = idx >> 3, q = idx & 7;
            int mloc = vr >> 5, xv = vr & 31;
            int h2 = hbase - 20 + 2 * (m0 + mloc);
            if (h2 >= 0 && h2 < 64) {
                int row = mloc * 56 + xv + 10;
                size_t so = SB + ((size_t)h2 * 32 + xv) * 256 + c0 + q * 8;
                uint32_t dst = (row >> 3) * 1024 + (row & 7) * 128 + ((q * 16) ^ ((row & 7) << 4));
                cp16(bb + OFF_B + dst, g_hi + so);
            }
        }
        asm volatile("cp.async.commit_group;");
    };

    stage(0, 0);

    for (int cc = 0; cc < 4; ++cc) {
        if (cc < 3) {
            stage(cc + 1, (cc + 1) & 1);
            asm volatile("cp.async.wait_group 1;");
        } else {
            asm volatile("cp.async.wait_group 0;");
        }
        __syncthreads();

        if (dyvalid) {
            const uint32_t bufb = sb + (cc & 1) * BUF;
            const uint32_t uA = bufb + OFF_A;
            const uint32_t uB = bufb + OFF_B;
#pragma unroll
            for (int s = 0; s < 4; ++s) {
                const uint32_t kb = 32 * s;
                uint32_t ah[2][4];
#pragma unroll
                for (int mt = 0; mt < 2; ++mt)
                    ldsm_x4(ah[mt][0], ah[mt][1], ah[mt][2], ah[mt][3],
                            uA + abase[mt] + ((kb + khA) ^ kxor));
                uint32_t bf[7][2];
#pragma unroll
                for (int p = 0; p < 3; ++p)
                    ldsm_x4(bf[2 * p][0], bf[2 * p][1], bf[2 * p + 1][0], bf[2 * p + 1][1],
                            uB + bbase[p] + ((kb + khB) ^ kxor));
                ldsm_x2(bf[6][0], bf[6][1], uB + bbase6 + ((kb + khB) ^ kxor));
#pragma unroll
                for (int mt = 0; mt < 2; ++mt)
#pragma unroll
                    for (int w = 0; w < 5; ++w)
                        mma_f16(acc[mt][w], ah[mt], bf[w + 2 * mt]);
            }
        }
        __syncthreads();
    }

    // ---- epilogue: per-warp smem [u:32][x:58], band gather, store
    if (dyvalid) {
        float* sD = (float*)(smem + wq * (32 * 58 * 4));
#pragma unroll
        for (int mt = 0; mt < 2; ++mt)
#pragma unroll
            for (int w = 0; w < 5; ++w) {
                const int nt = w + 2 * mt;
#pragma unroll
                for (int r = 0; r < 4; ++r) {
                    int u = 16 * mt + (lane >> 2) + 8 * (r >> 1);
                    int x = 8 * nt + 2 * (lane & 3) + (r & 1);
                    sD[u * 58 + x] = acc[mt][w][r];
                }
            }
        __syncwarp();

        const int hk = hbase + 2 * wr;
        const float scale = 1.0f / 256.0f;
        size_t ob = ((size_t)b * 441 + (size_t)dy * 21) * 4096 + (size_t)hk * 64 + wp + 2 * lane;
        const float* sr0 = sD + lane * 58 + lane;
#pragma unroll
        for (int j = 0; j < 21; ++j)
            out[ob + (size_t)j * 4096] = sr0[j] * scale;
    }
}

} // namespace

extern "C" void kernel_launch(void* const* d_in, const int* in_sizes, int n_in,
                              void* d_out, int out_size)
{
    const float* in1 = (const float*)d_in[0];
    const float* in2 = (const float*)d_in[1];
    float* out = (float*)d_out;

    cudaFuncSetAttribute(corr_mma_kernel,
                         cudaFuncAttributeMaxDynamicSharedMemorySize, SMEM_BYTES);

    dim3 cgrid(8, 64, 16);
    convert_kernel<<<cgrid, 256>>>(in1, in2);

    dim3 grid(12, 16, 16);
    corr_mma_kernel<<<grid, 256, SMEM_BYTES>>>(out);
}

// round 13
// speedup vs baseline: 5.0834x; 1.0135x over previous
#include <cuda_runtime.h>
#include <cuda_fp16.h>
#include <cstdint>

namespace {

// double-buffered smem layout (byte offsets within one buffer)
constexpr int OFF_A  = 0;
constexpr int A_TILE = 128 * 128;             // 128 rows x 128B (64 fp16)
constexpr int OFF_B  = OFF_A + A_TILE;        // 16384
constexpr int B_TILE = 112 * 128;             // 14336 (2 m x 56 x)
constexpr int BUF    = OFF_B + B_TILE;        // 30720 per buffer
constexpr int EPI_BYTES  = 8 * 32 * 58 * 4;   // 59392
constexpr int SMEM_BYTES = 2 * BUF;           // 61440 >= EPI_BYTES

// scratch: [z2 = tensor*16 + b*2 + wp][h][u][c] fp16
__device__ __align__(16) __half g_hi[2ull * 16 * 64 * 32 * 256];

__device__ __forceinline__ uint32_t smem_u32(const void* p) {
    uint32_t a;
    asm("{ .reg .u64 t; cvta.to.shared.u64 t, %1; cvt.u32.u64 %0, t; }" : "=r"(a) : "l"(p));
    return a;
}
__device__ __forceinline__ void ldsm_x4(uint32_t& r0, uint32_t& r1, uint32_t& r2, uint32_t& r3,
                                        uint32_t addr) {
    asm volatile("ldmatrix.sync.aligned.m8n8.x4.shared.b16 {%0,%1,%2,%3}, [%4];"
                 : "=r"(r0), "=r"(r1), "=r"(r2), "=r"(r3) : "r"(addr));
}
__device__ __forceinline__ void ldsm_x2(uint32_t& r0, uint32_t& r1, uint32_t addr) {
    asm volatile("ldmatrix.sync.aligned.m8n8.x2.shared.b16 {%0,%1}, [%2];"
                 : "=r"(r0), "=r"(r1) : "r"(addr));
}
__device__ __forceinline__ void mma_f16(float* d, const uint32_t* a, const uint32_t* b) {
    asm volatile("mma.sync.aligned.m16n8k16.row.col.f32.f16.f16.f32 "
                 "{%0,%1,%2,%3}, {%4,%5,%6,%7}, {%8,%9}, {%0,%1,%2,%3};"
                 : "+f"(d[0]), "+f"(d[1]), "+f"(d[2]), "+f"(d[3])
                 : "r"(a[0]), "r"(a[1]), "r"(a[2]), "r"(a[3]), "r"(b[0]), "r"(b[1]));
}
__device__ __forceinline__ void cp16(uint32_t dst, const void* src) {
    asm volatile("cp.async.ca.shared.global [%0], [%1], 16;" :: "r"(dst), "l"(src));
}

// ---------------- conversion: fp32 [b][c][h][w] -> fp16 [z2][h][u][c]
__global__ void __launch_bounds__(256)
convert_kernel(const float* __restrict__ in1, const float* __restrict__ in2)
{
    __shared__ float tile[32][65];
    const int cb = blockIdx.x;            // 0..7
    const int h  = blockIdx.y;            // 0..63
    const int z  = blockIdx.z;            // tensor*8 + b
    const float* src = (z < 8) ? in1 : in2;
    const int b = z & 7;
    const int t = threadIdx.x;

#pragma unroll
    for (int it = 0; it < 8; ++it) {
        int idx = t + 256 * it;
        int c = idx >> 6, w = idx & 63;
        tile[c][w] = src[(((size_t)b * 256 + cb * 32 + c) * 64 + h) * 64 + w];
    }
    __syncthreads();
#pragma unroll
    for (int it = 0; it < 8; ++it) {
        int idx = t + 256 * it;
        int row = idx >> 5, c = idx & 31;    // row = wp*32 + u
        int wp = row >> 5, u = row & 31;
        int w  = wp + 2 * u;
        int z2 = (z >> 3) * 16 + b * 2 + wp;
        size_t o = (((size_t)z2 * 64 + h) * 32 + u) * 256 + cb * 32 + c;
        g_hi[o] = __float2half(tile[c][w]);
    }
}

// ---------------- main: banded GEMM, fp16 mma.sync, 256 thr, 3 CTAs/SM (reg-capped)
__global__ void __launch_bounds__(256, 3)
corr_mma_kernel(float* __restrict__ out)
{
    extern __shared__ char smem[];
    const uint32_t sb = smem_u32(smem);
    const int tid  = threadIdx.x;
    const int lane = tid & 31;
    const int wq   = tid >> 5;        // 0..7
    const int wr   = wq & 3;          // k = wr
    const int wc   = wq >> 2;         // m = m0 + wc (0..1)

    const int mq = blockIdx.x;        // 0..11
    const int g  = blockIdx.y;        // 0..15
    const int z  = blockIdx.z;        // b*2 + wp
    const int b  = z >> 1, wp = z & 1;
    const int pi = g & 1, ig = g >> 1;
    const int hbase = pi + 8 * ig;    // h_k = hbase + 2k
    const int m0 = mq * 2;

    const int dy = m0 + wc - wr;
    const bool dyvalid = (dy >= 0) & (dy < 21);

    const size_t SA = (size_t)(b * 2 + wp) * (64 * 32 * 256);
    const size_t SB = (size_t)(16 + b * 2 + wp) * (64 * 32 * 256);

    // ldmatrix per-lane address components
    const int l7 = lane & 7;
    const int lh = (lane >> 3) & 1;
    const int lq = lane >> 4;
    const uint32_t kxor = l7 << 4;
    const uint32_t khA  = lq * 16;
    const uint32_t khB  = lh * 16;
    uint32_t abase[2], bbase[3], bbase6;
#pragma unroll
    for (int mt = 0; mt < 2; ++mt) {
        int row = 32 * wr + 16 * mt + l7 + 8 * lh;
        abase[mt] = (row >> 3) * 1024 + l7 * 128;
    }
#pragma unroll
    for (int p = 0; p < 3; ++p) {
        int row = 56 * wc + 16 * p + 8 * lq + l7;
        bbase[p] = (row >> 3) * 1024 + l7 * 128;
    }
    {
        int row = 56 * wc + 48 + l7;
        bbase6 = (row >> 3) * 1024 + l7 * 128;
    }

    float acc[2][5][4];                // [mt][window w -> nt = w + 2*mt]
#pragma unroll
    for (int mt = 0; mt < 2; ++mt)
#pragma unroll
        for (int w = 0; w < 5; ++w)
#pragma unroll
            for (int r = 0; r < 4; ++r) acc[mt][w][r] = 0.f;

    // ---- zero B pad/OOB rows in both buffers once (row set is chunk-invariant)
    {
        float4 zz = make_float4(0.f, 0.f, 0.f, 0.f);
        for (int idx = tid; idx < 2 * 112 * 8; idx += 256) {
            int bi = idx >= 112 * 8;
            int k2 = idx - bi * 112 * 8;
            int row = k2 >> 3, q = k2 & 7;
            uint32_t dst = (row >> 3) * 1024 + (row & 7) * 128 + ((q * 16) ^ ((row & 7) << 4));
            *(float4*)(smem + bi * BUF + OFF_B + dst) = zz;
        }
    }
    __syncthreads();

    auto stage = [&](int cc, int bsel) {
        const int c0 = cc * 64;
        const uint32_t bb = sb + bsel * BUF;
        // A: 128 rows x 8 quads = 1024 cp.async over 256 threads
#pragma unroll
        for (int it = 0; it < 4; ++it) {
            int idx = tid + 256 * it;
            int row = idx >> 3, q = idx & 7;
            int k = row >> 5, u = row & 31;
            int h = hbase + 2 * k;
            size_t so = SA + ((size_t)h * 32 + u) * 256 + c0 + q * 8;
            uint32_t dst = (row >> 3) * 1024 + (row & 7) * 128 + ((q * 16) ^ ((row & 7) << 4));
            cp16(bb + OFF_A + dst, g_hi + so);
        }
        // B: 64 valid rows (2 m x 32 xv) x 8 quads; OOB h2 rows stay zero
#pragma unroll
        for (int it = 0; it < 2; ++it) {
            int idx = tid + 256 * it;
            int vr = idx >> 3, q = idx & 7;
            int mloc = vr >> 5, xv = vr & 31;
            int h2 = hbase - 20 + 2 * (m0 + mloc);
            if (h2 >= 0 && h2 < 64) {
                int row = mloc * 56 + xv + 10;
                size_t so = SB + ((size_t)h2 * 32 + xv) * 256 + c0 + q * 8;
                uint32_t dst = (row >> 3) * 1024 + (row & 7) * 128 + ((q * 16) ^ ((row & 7) << 4));
                cp16(bb + OFF_B + dst, g_hi + so);
            }
        }
        asm volatile("cp.async.commit_group;");
    };

    stage(0, 0);

    for (int cc = 0; cc < 4; ++cc) {
        if (cc < 3) {
            stage(cc + 1, (cc + 1) & 1);
            asm volatile("cp.async.wait_group 1;");
        } else {
            asm volatile("cp.async.wait_group 0;");
        }
        __syncthreads();

        if (dyvalid) {
            const uint32_t bufb = sb + (cc & 1) * BUF;
            const uint32_t uA = bufb + OFF_A;
            const uint32_t uB = bufb + OFF_B;
#pragma unroll
            for (int s = 0; s < 4; ++s) {
                const uint32_t kb = 32 * s;
                uint32_t ah[2][4];
#pragma unroll
                for (int mt = 0; mt < 2; ++mt)
                    ldsm_x4(ah[mt][0], ah[mt][1], ah[mt][2], ah[mt][3],
                            uA + abase[mt] + ((kb + khA) ^ kxor));
                uint32_t bf[7][2];
#pragma unroll
                for (int p = 0; p < 3; ++p)
                    ldsm_x4(bf[2 * p][0], bf[2 * p][1], bf[2 * p + 1][0], bf[2 * p + 1][1],
                            uB + bbase[p] + ((kb + khB) ^ kxor));
                ldsm_x2(bf[6][0], bf[6][1], uB + bbase6 + ((kb + khB) ^ kxor));
#pragma unroll
                for (int mt = 0; mt < 2; ++mt)
#pragma unroll
                    for (int w = 0; w < 5; ++w)
                        mma_f16(acc[mt][w], ah[mt], bf[w + 2 * mt]);
            }
        }
        __syncthreads();
    }

    // ---- epilogue: per-warp smem [u:32][x:58], band gather, store
    if (dyvalid) {
        float* sD = (float*)(smem + wq * (32 * 58 * 4));
#pragma unroll
        for (int mt = 0; mt < 2; ++mt)
#pragma unroll
            for (int w = 0; w < 5; ++w) {
                const int nt = w + 2 * mt;
#pragma unroll
                for (int r = 0; r < 4; ++r) {
                    int u = 16 * mt + (lane >> 2) + 8 * (r >> 1);
                    int x = 8 * nt + 2 * (lane & 3) + (r & 1);
                    sD[u * 58 + x] = acc[mt][w][r];
                }
            }
        __syncwarp();

        const int hk = hbase + 2 * wr;
        const float scale = 1.0f / 256.0f;
        size_t ob = ((size_t)b * 441 + (size_t)dy * 21) * 4096 + (size_t)hk * 64 + wp + 2 * lane;
        const float* sr0 = sD + lane * 58 + lane;
#pragma unroll
        for (int j = 0; j < 21; ++j)
            out[ob + (size_t)j * 4096] = sr0[j] * scale;
    }
}

} // namespace

extern "C" void kernel_launch(void* const* d_in, const int* in_sizes, int n_in,
                              void* d_out, int out_size)
{
    const float* in1 = (const float*)d_in[0];
    const float* in2 = (const float*)d_in[1];
    float* out = (float*)d_out;

    cudaFuncSetAttribute(corr_mma_kernel,
                         cudaFuncAttributeMaxDynamicSharedMemorySize, SMEM_BYTES);

    dim3 cgrid(8, 64, 16);
    convert_kernel<<<cgrid, 256>>>(in1, in2);

    dim3 grid(12, 16, 16);
    corr_mma_kernel<<<grid, 256, SMEM_BYTES>>>(out);
}

// round 14
// speedup vs baseline: 5.3377x; 1.0500x over previous
#include <cuda_runtime.h>
#include <cuda_fp16.h>
#include <cstdint>

namespace {

// double-buffered smem layout (byte offsets within one buffer)
constexpr int OFF_A  = 0;
constexpr int A_TILE = 128 * 128;             // 128 rows x 128B (64 fp16)
constexpr int OFF_B  = OFF_A + A_TILE;        // 16384
constexpr int B_TILE = 224 * 128;             // 28672 (4 m x 56 x)
constexpr int BUF    = OFF_B + B_TILE;        // 45056 per buffer
constexpr int SMEM_BYTES = 2 * BUF;           // 90112 (>= epilogue 59392)

// scratch: [z2 = tensor*16 + b*2 + wp][h][u][c] fp16
__device__ __align__(16) __half g_hi[2ull * 16 * 64 * 32 * 256];

__device__ __forceinline__ uint32_t smem_u32(const void* p) {
    uint32_t a;
    asm("{ .reg .u64 t; cvta.to.shared.u64 t, %1; cvt.u32.u64 %0, t; }" : "=r"(a) : "l"(p));
    return a;
}
__device__ __forceinline__ void ldsm_x4(uint32_t& r0, uint32_t& r1, uint32_t& r2, uint32_t& r3,
                                        uint32_t addr) {
    asm volatile("ldmatrix.sync.aligned.m8n8.x4.shared.b16 {%0,%1,%2,%3}, [%4];"
                 : "=r"(r0), "=r"(r1), "=r"(r2), "=r"(r3) : "r"(addr));
}
__device__ __forceinline__ void ldsm_x2(uint32_t& r0, uint32_t& r1, uint32_t addr) {
    asm volatile("ldmatrix.sync.aligned.m8n8.x2.shared.b16 {%0,%1}, [%2];"
                 : "=r"(r0), "=r"(r1) : "r"(addr));
}
__device__ __forceinline__ void mma_f16(float* d, const uint32_t* a, const uint32_t* b) {
    asm volatile("mma.sync.aligned.m16n8k16.row.col.f32.f16.f16.f32 "
                 "{%0,%1,%2,%3}, {%4,%5,%6,%7}, {%8,%9}, {%0,%1,%2,%3};"
                 : "+f"(d[0]), "+f"(d[1]), "+f"(d[2]), "+f"(d[3])
                 : "r"(a[0]), "r"(a[1]), "r"(a[2]), "r"(a[3]), "r"(b[0]), "r"(b[1]));
}
__device__ __forceinline__ void cp16(uint32_t dst, const void* src) {
    asm volatile("cp.async.ca.shared.global [%0], [%1], 16;" :: "r"(dst), "l"(src));
}

// ---------------- conversion: fp32 [b][c][h][w] -> fp16 [z2][h][u][c]
__global__ void __launch_bounds__(256)
convert_kernel(const float* __restrict__ in1, const float* __restrict__ in2)
{
    __shared__ float tile[32][65];
    const int cb = blockIdx.x;            // 0..7
    const int h  = blockIdx.y;            // 0..63
    const int z  = blockIdx.z;            // tensor*8 + b
    const float* src = (z < 8) ? in1 : in2;
    const int b = z & 7;
    const int t = threadIdx.x;

#pragma unroll
    for (int it = 0; it < 8; ++it) {
        int idx = t + 256 * it;
        int c = idx >> 6, w = idx & 63;
        tile[c][w] = src[(((size_t)b * 256 + cb * 32 + c) * 64 + h) * 64 + w];
    }
    __syncthreads();
#pragma unroll
    for (int it = 0; it < 8; ++it) {
        int idx = t + 256 * it;
        int row = idx >> 5, c = idx & 31;    // row = wp*32 + u
        int wp = row >> 5, u = row & 31;
        int w  = wp + 2 * u;
        int z2 = (z >> 3) * 16 + b * 2 + wp;
        size_t o = (((size_t)z2 * 64 + h) * 32 + u) * 256 + cb * 32 + c;
        g_hi[o] = __float2half(tile[c][w]);
    }
}

// ---------------- main: banded GEMM, fp16 mma.sync, warp tile M=64(2k)xN=56
__global__ void __launch_bounds__(256, 2)
corr_mma_kernel(float* __restrict__ out)
{
    extern __shared__ char smem[];
    const uint32_t sb = smem_u32(smem);
    const int tid  = threadIdx.x;
    const int lane = tid & 31;
    const int wq   = tid >> 5;        // 0..7
    const int wc   = wq & 3;          // m = m0 + wc
    const int kp   = wq >> 2;         // k pair: k = 2*kp + kk

    const int mq = blockIdx.x;        // 0..5
    const int g  = blockIdx.y;        // 0..15
    const int z  = blockIdx.z;        // b*2 + wp
    const int b  = z >> 1, wp = z & 1;
    const int pi = g & 1, ig = g >> 1;
    const int hbase = pi + 8 * ig;    // h_k = hbase + 2k
    const int m0 = mq * 4;

    const int m = m0 + wc;
    int dyk[2];
    bool vk[2];
#pragma unroll
    for (int kk = 0; kk < 2; ++kk) {
        dyk[kk] = m - (2 * kp + kk);
        vk[kk] = (dyk[kk] >= 0) & (dyk[kk] < 21);
    }
    const bool anyv = vk[0] | vk[1];

    const size_t SA = (size_t)(b * 2 + wp) * (64 * 32 * 256);
    const size_t SB = (size_t)(16 + b * 2 + wp) * (64 * 32 * 256);

    // ldmatrix per-lane address components
    const int l7 = lane & 7;
    const int lh = (lane >> 3) & 1;
    const int lq = lane >> 4;
    const uint32_t kxor = l7 << 4;
    const uint32_t khA  = lq * 16;
    const uint32_t khB  = lh * 16;
    uint32_t abase[2][2], bbase[3], bbase6;
#pragma unroll
    for (int kk = 0; kk < 2; ++kk)
#pragma unroll
        for (int mt = 0; mt < 2; ++mt) {
            int row = 32 * (2 * kp + kk) + 16 * mt + l7 + 8 * lh;
            abase[kk][mt] = (row >> 3) * 1024 + l7 * 128;
        }
#pragma unroll
    for (int p = 0; p < 3; ++p) {
        int row = 56 * wc + 16 * p + 8 * lq + l7;
        bbase[p] = (row >> 3) * 1024 + l7 * 128;
    }
    {
        int row = 56 * wc + 48 + l7;
        bbase6 = (row >> 3) * 1024 + l7 * 128;
    }

    float acc[2][2][5][4];             // [kk][mt][window w -> nt = w + 2*mt][reg]
#pragma unroll
    for (int kk = 0; kk < 2; ++kk)
#pragma unroll
        for (int mt = 0; mt < 2; ++mt)
#pragma unroll
            for (int w = 0; w < 5; ++w)
#pragma unroll
                for (int r = 0; r < 4; ++r) acc[kk][mt][w][r] = 0.f;

    // ---- zero entire B regions of both buffers once (pad/OOB rows stay zero)
    {
        float4 zz = make_float4(0.f, 0.f, 0.f, 0.f);
        for (int idx = tid; idx < 2 * 224 * 8; idx += 256) {
            int bi = idx >= 224 * 8;
            int k2 = idx - bi * 224 * 8;
            *(float4*)(smem + bi * BUF + OFF_B + k2 * 16) = zz;
        }
    }

    auto stage = [&](int cc, int bsel) {
        const int c0 = cc * 64;
        const uint32_t bb = sb + bsel * BUF;
        // A: 128 rows x 8 quads = 1024 cp.async over 256 threads
#pragma unroll
        for (int it = 0; it < 4; ++it) {
            int idx = tid + 256 * it;
            int row = idx >> 3, q = idx & 7;
            int k = row >> 5, u = row & 31;
            int h = hbase + 2 * k;
            size_t so = SA + ((size_t)h * 32 + u) * 256 + c0 + q * 8;
            uint32_t dst = (row >> 3) * 1024 + (row & 7) * 128 + ((q * 16) ^ ((row & 7) << 4));
            cp16(bb + OFF_A + dst, g_hi + so);
        }
        // B: 128 valid rows (4 m x 32 xv) x 8 quads; OOB h2 rows stay zero
#pragma unroll
        for (int it = 0; it < 4; ++it) {
            int idx = tid + 256 * it;
            int vr = idx >> 3, q = idx & 7;
            int mloc = vr >> 5, xv = vr & 31;
            int h2 = hbase - 20 + 2 * (m0 + mloc);
            if (h2 >= 0 && h2 < 64) {
                int row = mloc * 56 + xv + 10;
                size_t so = SB + ((size_t)h2 * 32 + xv) * 256 + c0 + q * 8;
                uint32_t dst = (row >> 3) * 1024 + (row & 7) * 128 + ((q * 16) ^ ((row & 7) << 4));
                cp16(bb + OFF_B + dst, g_hi + so);
            }
        }
        asm volatile("cp.async.commit_group;");
    };

    // NOTE: zero-stores above are ordered before stage(0)'s cp.async to the
    // same region? They target disjoint addresses (valid rows vs pad rows),
    // and visibility to other warps is established by the first __syncthreads.
    stage(0, 0);

    for (int cc = 0; cc < 4; ++cc) {
        asm volatile("cp.async.wait_group 0;");
        __syncthreads();
        if (cc < 3) stage(cc + 1, (cc + 1) & 1);   // overlaps compute below

        if (anyv) {
            const uint32_t bufb = sb + (cc & 1) * BUF;
            const uint32_t uA = bufb + OFF_A;
            const uint32_t uB = bufb + OFF_B;
#pragma unroll
            for (int s = 0; s < 4; ++s) {
                const uint32_t kb = 32 * s;
                uint32_t bf[7][2];
#pragma unroll
                for (int p = 0; p < 3; ++p)
                    ldsm_x4(bf[2 * p][0], bf[2 * p][1], bf[2 * p + 1][0], bf[2 * p + 1][1],
                            uB + bbase[p] + ((kb + khB) ^ kxor));
                ldsm_x2(bf[6][0], bf[6][1], uB + bbase6 + ((kb + khB) ^ kxor));
#pragma unroll
                for (int kk = 0; kk < 2; ++kk) {
                    if (!vk[kk]) continue;
                    uint32_t ah[2][4];
#pragma unroll
                    for (int mt = 0; mt < 2; ++mt)
                        ldsm_x4(ah[mt][0], ah[mt][1], ah[mt][2], ah[mt][3],
                                uA + abase[kk][mt] + ((kb + khA) ^ kxor));
#pragma unroll
                    for (int mt = 0; mt < 2; ++mt)
#pragma unroll
                        for (int w = 0; w < 5; ++w)
                            mma_f16(acc[kk][mt][w], ah[mt], bf[w + 2 * mt]);
                }
            }
        }
    }
    __syncthreads();   // all compute done before epilogue reuses smem

    // ---- epilogue: per-warp smem [u:32][x:58]; one pass per valid kk
    float* sD = (float*)(smem + wq * (32 * 58 * 4));
    const float scale = 1.0f / 256.0f;
#pragma unroll
    for (int kk = 0; kk < 2; ++kk) {
        if (!vk[kk]) continue;
#pragma unroll
        for (int mt = 0; mt < 2; ++mt)
#pragma unroll
            for (int w = 0; w < 5; ++w) {
                const int nt = w + 2 * mt;
#pragma unroll
                for (int r = 0; r < 4; ++r) {
                    int u = 16 * mt + (lane >> 2) + 8 * (r >> 1);
                    int x = 8 * nt + 2 * (lane & 3) + (r & 1);
                    sD[u * 58 + x] = acc[kk][mt][w][r];
                }
            }
        __syncwarp();

        const int hk = hbase + 2 * (2 * kp + kk);
        size_t ob = ((size_t)b * 441 + (size_t)dyk[kk] * 21) * 4096
                  + (size_t)hk * 64 + wp + 2 * lane;
        const float* sr0 = sD + lane * 58 + lane;
#pragma unroll
        for (int j = 0; j < 21; ++j)
            out[ob + (size_t)j * 4096] = sr0[j] * scale;
        __syncwarp();
    }
}

} // namespace

extern "C" void kernel_launch(void* const* d_in, const int* in_sizes, int n_in,
                              void* d_out, int out_size)
{
    const float* in1 = (const float*)d_in[0];
    const float* in2 = (const float*)d_in[1];
    float* out = (float*)d_out;

    cudaFuncSetAttribute(corr_mma_kernel,
                         cudaFuncAttributeMaxDynamicSharedMemorySize, SMEM_BYTES);

    dim3 cgrid(8, 64, 16);
    convert_kernel<<<cgrid, 256>>>(in1, in2);

    dim3 grid(6, 16, 16);
    corr_mma_kernel<<<grid, 256, SMEM_BYTES>>>(out);
}

// round 15
// speedup vs baseline: 5.7039x; 1.0686x over previous
#include <cuda_runtime.h>
#include <cuda_fp16.h>
#include <cstdint>

namespace {

// double-buffered smem layout (byte offsets within one buffer)
constexpr int OFF_A  = 0;
constexpr int A_TILE = 128 * 128;             // 128 rows x 128B (64 fp16)
constexpr int OFF_B  = OFF_A + A_TILE;        // 16384
constexpr int B_TILE = 224 * 128;             // 28672 (4 m x 56 x)
constexpr int BUF    = OFF_B + B_TILE;        // 45056 per buffer
constexpr int SMEM_BYTES = 2 * BUF;           // 90112 (>= epilogue 8*8064=64512)

// scratch: [z2 = tensor*16 + b*2 + wp][h][u][c] fp16
__device__ __align__(16) __half g_hi[2ull * 16 * 64 * 32 * 256];

__device__ __forceinline__ uint32_t smem_u32(const void* p) {
    uint32_t a;
    asm("{ .reg .u64 t; cvta.to.shared.u64 t, %1; cvt.u32.u64 %0, t; }" : "=r"(a) : "l"(p));
    return a;
}
__device__ __forceinline__ void ldsm_x4(uint32_t& r0, uint32_t& r1, uint32_t& r2, uint32_t& r3,
                                        uint32_t addr) {
    asm volatile("ldmatrix.sync.aligned.m8n8.x4.shared.b16 {%0,%1,%2,%3}, [%4];"
                 : "=r"(r0), "=r"(r1), "=r"(r2), "=r"(r3) : "r"(addr));
}
__device__ __forceinline__ void ldsm_x2(uint32_t& r0, uint32_t& r1, uint32_t addr) {
    asm volatile("ldmatrix.sync.aligned.m8n8.x2.shared.b16 {%0,%1}, [%2];"
                 : "=r"(r0), "=r"(r1) : "r"(addr));
}
__device__ __forceinline__ void mma_f16(float* d, const uint32_t* a, const uint32_t* b) {
    asm volatile("mma.sync.aligned.m16n8k16.row.col.f32.f16.f16.f32 "
                 "{%0,%1,%2,%3}, {%4,%5,%6,%7}, {%8,%9}, {%0,%1,%2,%3};"
                 : "+f"(d[0]), "+f"(d[1]), "+f"(d[2]), "+f"(d[3])
                 : "r"(a[0]), "r"(a[1]), "r"(a[2]), "r"(a[3]), "r"(b[0]), "r"(b[1]));
}
__device__ __forceinline__ void cp16(uint32_t dst, const void* src) {
    asm volatile("cp.async.ca.shared.global [%0], [%1], 16;" :: "r"(dst), "l"(src));
}

// ---------------- conversion: fp32 [b][c][h][w] -> fp16 [z2][h][u][c]
__global__ void __launch_bounds__(256)
convert_kernel(const float* __restrict__ in1, const float* __restrict__ in2)
{
    __shared__ float tile[32][65];
    const int cb = blockIdx.x;            // 0..7
    const int h  = blockIdx.y;            // 0..63
    const int z  = blockIdx.z;            // tensor*8 + b
    const float* src = (z < 8) ? in1 : in2;
    const int b = z & 7;
    const int t = threadIdx.x;

#pragma unroll
    for (int it = 0; it < 8; ++it) {
        int idx = t + 256 * it;
        int c = idx >> 6, w = idx & 63;
        tile[c][w] = src[(((size_t)b * 256 + cb * 32 + c) * 64 + h) * 64 + w];
    }
    __syncthreads();
#pragma unroll
    for (int it = 0; it < 4; ++it) {
        int idx = t + 256 * it;              // 0..1023 half2 units
        int row = idx >> 4, cp = idx & 15;   // row = wp*32 + u, c = 2*cp
        int wp = row >> 5, u = row & 31;
        int w  = wp + 2 * u;
        __half2 h2 = __floats2half2_rn(tile[2 * cp][w], tile[2 * cp + 1][w]);
        int z2 = (z >> 3) * 16 + b * 2 + wp;
        size_t o = (((size_t)z2 * 64 + h) * 32 + u) * 256 + cb * 32 + 2 * cp;
        *(__half2*)(g_hi + o) = h2;
    }
}

// ---------------- main: banded GEMM, fp16 mma.sync, warp tile M=64(2k)xN=56
__global__ void __launch_bounds__(256, 2)
corr_mma_kernel(float* __restrict__ out)
{
    extern __shared__ char smem[];
    const uint32_t sb = smem_u32(smem);
    const int tid  = threadIdx.x;
    const int lane = tid & 31;
    const int wq   = tid >> 5;        // 0..7
    const int wc   = wq & 3;          // m = m0 + wc
    const int kp   = wq >> 2;         // k pair: k = 2*kp + kk

    const int mq = blockIdx.x;        // 0..5
    const int g  = blockIdx.y;        // 0..15
    const int z  = blockIdx.z;        // b*2 + wp
    const int b  = z >> 1, wp = z & 1;
    const int pi = g & 1, ig = g >> 1;
    const int hbase = pi + 8 * ig;    // h_k = hbase + 2k
    const int m0 = mq * 4;

    const int m = m0 + wc;
    int dyk[2];
    bool vk[2];
#pragma unroll
    for (int kk = 0; kk < 2; ++kk) {
        dyk[kk] = m - (2 * kp + kk);
        vk[kk] = (dyk[kk] >= 0) & (dyk[kk] < 21);
    }
    const bool anyv = vk[0] | vk[1];

    const size_t SA = (size_t)(b * 2 + wp) * (64 * 32 * 256);
    const size_t SB = (size_t)(16 + b * 2 + wp) * (64 * 32 * 256);

    // ldmatrix per-lane address components
    const int l7 = lane & 7;
    const int lh = (lane >> 3) & 1;
    const int lq = lane >> 4;
    const uint32_t kxor = l7 << 4;
    const uint32_t khA  = lq * 16;
    const uint32_t khB  = lh * 16;
    uint32_t abase[2][2], bbase[3], bbase6;
#pragma unroll
    for (int kk = 0; kk < 2; ++kk)
#pragma unroll
        for (int mt = 0; mt < 2; ++mt) {
            int row = 32 * (2 * kp + kk) + 16 * mt + l7 + 8 * lh;
            abase[kk][mt] = (row >> 3) * 1024 + l7 * 128;
        }
#pragma unroll
    for (int p = 0; p < 3; ++p) {
        int row = 56 * wc + 16 * p + 8 * lq + l7;
        bbase[p] = (row >> 3) * 1024 + l7 * 128;
    }
    {
        int row = 56 * wc + 48 + l7;
        bbase6 = (row >> 3) * 1024 + l7 * 128;
    }

    float acc[2][2][5][4];             // [kk][mt][window w -> nt = w + 2*mt][reg]
#pragma unroll
    for (int kk = 0; kk < 2; ++kk)
#pragma unroll
        for (int mt = 0; mt < 2; ++mt)
#pragma unroll
            for (int w = 0; w < 5; ++w)
#pragma unroll
                for (int r = 0; r < 4; ++r) acc[kk][mt][w][r] = 0.f;

    // ---- zero entire B regions of both buffers once (pad/OOB rows stay zero)
    {
        float4 zz = make_float4(0.f, 0.f, 0.f, 0.f);
        for (int idx = tid; idx < 2 * 224 * 8; idx += 256) {
            int bi = idx >= 224 * 8;
            int k2 = idx - bi * 224 * 8;
            *(float4*)(smem + bi * BUF + OFF_B + k2 * 16) = zz;
        }
    }

    auto stage = [&](int cc, int bsel) {
        const int c0 = cc * 64;
        const uint32_t bb = sb + bsel * BUF;
        // A: 128 rows x 8 quads = 1024 cp.async over 256 threads
#pragma unroll
        for (int it = 0; it < 4; ++it) {
            int idx = tid + 256 * it;
            int row = idx >> 3, q = idx & 7;
            int k = row >> 5, u = row & 31;
            int h = hbase + 2 * k;
            size_t so = SA + ((size_t)h * 32 + u) * 256 + c0 + q * 8;
            uint32_t dst = (row >> 3) * 1024 + (row & 7) * 128 + ((q * 16) ^ ((row & 7) << 4));
            cp16(bb + OFF_A + dst, g_hi + so);
        }
        // B: 128 valid rows (4 m x 32 xv) x 8 quads; OOB h2 rows stay zero
#pragma unroll
        for (int it = 0; it < 4; ++it) {
            int idx = tid + 256 * it;
            int vr = idx >> 3, q = idx & 7;
            int mloc = vr >> 5, xv = vr & 31;
            int h2 = hbase - 20 + 2 * (m0 + mloc);
            if (h2 >= 0 && h2 < 64) {
                int row = mloc * 56 + xv + 10;
                size_t so = SB + ((size_t)h2 * 32 + xv) * 256 + c0 + q * 8;
                uint32_t dst = (row >> 3) * 1024 + (row & 7) * 128 + ((q * 16) ^ ((row & 7) << 4));
                cp16(bb + OFF_B + dst, g_hi + so);
            }
        }
        asm volatile("cp.async.commit_group;");
    };

    stage(0, 0);

    for (int cc = 0; cc < 4; ++cc) {
        asm volatile("cp.async.wait_group 0;");
        __syncthreads();
        if (cc < 3) stage(cc + 1, (cc + 1) & 1);   // overlaps compute below

        if (anyv) {
            const uint32_t bufb = sb + (cc & 1) * BUF;
            const uint32_t uA = bufb + OFF_A;
            const uint32_t uB = bufb + OFF_B;
#pragma unroll
            for (int s = 0; s < 4; ++s) {
                const uint32_t kb = 32 * s;
                uint32_t bf[7][2];
#pragma unroll
                for (int p = 0; p < 3; ++p)
                    ldsm_x4(bf[2 * p][0], bf[2 * p][1], bf[2 * p + 1][0], bf[2 * p + 1][1],
                            uB + bbase[p] + ((kb + khB) ^ kxor));
                ldsm_x2(bf[6][0], bf[6][1], uB + bbase6 + ((kb + khB) ^ kxor));
#pragma unroll
                for (int kk = 0; kk < 2; ++kk) {
                    if (!vk[kk]) continue;
                    uint32_t ah[2][4];
#pragma unroll
                    for (int mt = 0; mt < 2; ++mt)
                        ldsm_x4(ah[mt][0], ah[mt][1], ah[mt][2], ah[mt][3],
                                uA + abase[kk][mt] + ((kb + khA) ^ kxor));
#pragma unroll
                    for (int mt = 0; mt < 2; ++mt)
#pragma unroll
                        for (int w = 0; w < 5; ++w)
                            mma_f16(acc[kk][mt][w], ah[mt], bf[w + 2 * mt]);
                }
            }
        }
    }
    __syncthreads();   // all compute done before epilogue reuses smem

    // ---- epilogue: per-warp smem [x:56][u:32] stride 36 (conflict-free STS/LDS)
    float* sD = (float*)(smem + wq * (56 * 36 * 4));
    const float scale = 1.0f / 256.0f;
#pragma unroll
    for (int kk = 0; kk < 2; ++kk) {
        if (!vk[kk]) continue;
#pragma unroll
        for (int mt = 0; mt < 2; ++mt)
#pragma unroll
            for (int w = 0; w < 5; ++w) {
                const int nt = w + 2 * mt;
#pragma unroll
                for (int r = 0; r < 4; ++r) {
                    int u = 16 * mt + (lane >> 2) + 8 * (r >> 1);
                    int x = 8 * nt + 2 * (lane & 3) + (r & 1);
                    sD[x * 36 + u] = acc[kk][mt][w][r];
                }
            }
        __syncwarp();

        const int hk = hbase + 2 * (2 * kp + kk);
        size_t ob = ((size_t)b * 441 + (size_t)dyk[kk] * 21) * 4096
                  + (size_t)hk * 64 + wp + 2 * lane;
#pragma unroll
        for (int j = 0; j < 21; ++j)
            out[ob + (size_t)j * 4096] = sD[(lane + j) * 36 + lane] * scale;
        __syncwarp();
    }
}

} // namespace

extern "C" void kernel_launch(void* const* d_in, const int* in_sizes, int n_in,
                              void* d_out, int out_size)
{
    const float* in1 = (const float*)d_in[0];
    const float* in2 = (const float*)d_in[1];
    float* out = (float*)d_out;

    cudaFuncSetAttribute(corr_mma_kernel,
                         cudaFuncAttributeMaxDynamicSharedMemorySize, SMEM_BYTES);

    dim3 cgrid(8, 64, 16);
    convert_kernel<<<cgrid, 256>>>(in1, in2);

    dim3 grid(6, 16, 16);
    corr_mma_kernel<<<grid, 256, SMEM_BYTES>>>(out);
}

// round 16
// speedup vs baseline: 5.8754x; 1.0301x over previous
#include <cuda_runtime.h>
#include <cuda_fp16.h>
#include <cstdint>

namespace {

// double-buffered smem layout (byte offsets within one buffer)
constexpr int OFF_A  = 0;
constexpr int A_TILE = 128 * 128;             // 128 rows x 128B (64 fp16)
constexpr int OFF_B  = OFF_A + A_TILE;        // 16384
constexpr int B_TILE = 224 * 128;             // 28672 (4 m x 56 x)
constexpr int BUF    = OFF_B + B_TILE;        // 45056 per buffer
constexpr int SMEM_BYTES = 2 * BUF;           // 90112 (>= epilogue 8*9216=73728)

// scratch: [z2 = tensor*16 + b*2 + wp][h][u][c] fp16
__device__ __align__(16) __half g_hi[2ull * 16 * 64 * 32 * 256];

__device__ __forceinline__ uint32_t smem_u32(const void* p) {
    uint32_t a;
    asm("{ .reg .u64 t; cvta.to.shared.u64 t, %1; cvt.u32.u64 %0, t; }" : "=r"(a) : "l"(p));
    return a;
}
__device__ __forceinline__ void ldsm_x4(uint32_t& r0, uint32_t& r1, uint32_t& r2, uint32_t& r3,
                                        uint32_t addr) {
    asm volatile("ldmatrix.sync.aligned.m8n8.x4.shared.b16 {%0,%1,%2,%3}, [%4];"
                 : "=r"(r0), "=r"(r1), "=r"(r2), "=r"(r3) : "r"(addr));
}
__device__ __forceinline__ void ldsm_x2(uint32_t& r0, uint32_t& r1, uint32_t addr) {
    asm volatile("ldmatrix.sync.aligned.m8n8.x2.shared.b16 {%0,%1}, [%2];"
                 : "=r"(r0), "=r"(r1) : "r"(addr));
}
__device__ __forceinline__ void mma_f16(float* d, const uint32_t* a, const uint32_t* b) {
    asm volatile("mma.sync.aligned.m16n8k16.row.col.f32.f16.f16.f32 "
                 "{%0,%1,%2,%3}, {%4,%5,%6,%7}, {%8,%9}, {%0,%1,%2,%3};"
                 : "+f"(d[0]), "+f"(d[1]), "+f"(d[2]), "+f"(d[3])
                 : "r"(a[0]), "r"(a[1]), "r"(a[2]), "r"(a[3]), "r"(b[0]), "r"(b[1]));
}
__device__ __forceinline__ void cp16(uint32_t dst, const void* src) {
    asm volatile("cp.async.cg.shared.global [%0], [%1], 16;" :: "r"(dst), "l"(src));
}

// ---------------- conversion: fp32 [b][c][h][w] -> fp16 [z2][h][u][c]
__global__ void __launch_bounds__(256)
convert_kernel(const float* __restrict__ in1, const float* __restrict__ in2)
{
    __shared__ float tile[32 * 65];
    const int cb = blockIdx.x;            // 0..7
    const int h  = blockIdx.y;            // 0..63
    const int z  = blockIdx.z;            // tensor*8 + b
    const float* src = (z < 8) ? in1 : in2;
    const int b = z & 7;
    const int t = threadIdx.x;

#pragma unroll
    for (int it = 0; it < 8; ++it) {
        int idx = t + 256 * it;
        int c = idx >> 6, w = idx & 63;
        tile[c * 65 + w] = src[(((size_t)b * 256 + cb * 32 + c) * 64 + h) * 64 + w];
    }
    __syncthreads();
    // phase 2: units = (row 0..63, cquad 0..7); 4 channels per thread, STG.64
#pragma unroll
    for (int it = 0; it < 2; ++it) {
        int idx = t + 256 * it;
        int q   = idx & 7;                   // channel quad within 32-c slice
        int row = idx >> 3;                  // wp*32 + u
        int wp = row >> 5, u = row & 31;
        int w  = wp + 2 * u;
        __half2 h2[2];
        h2[0] = __floats2half2_rn(tile[(4 * q + 0) * 65 + w], tile[(4 * q + 1) * 65 + w]);
        h2[1] = __floats2half2_rn(tile[(4 * q + 2) * 65 + w], tile[(4 * q + 3) * 65 + w]);
        int z2 = (z >> 3) * 16 + b * 2 + wp;
        size_t o = (((size_t)z2 * 64 + h) * 32 + u) * 256 + cb * 32 + 4 * q;
        *(float2*)(g_hi + o) = *(float2*)h2;
    }
}

// ---------------- main: banded GEMM, fp16 mma.sync, warp tile M=64(2k)xN=56
__global__ void __launch_bounds__(256, 2)
corr_mma_kernel(float* __restrict__ out)
{
    extern __shared__ char smem[];
    const uint32_t sb = smem_u32(smem);
    const int tid  = threadIdx.x;
    const int lane = tid & 31;
    const int wq   = tid >> 5;        // 0..7
    const int wc   = wq & 3;          // m = m0 + wc
    const int kp   = wq >> 2;         // k pair: k = 2*kp + kk

    const int mq = blockIdx.x;        // 0..5
    const int g  = blockIdx.y;        // 0..15
    const int z  = blockIdx.z;        // b*2 + wp
    const int b  = z >> 1, wp = z & 1;
    const int pi = g & 1, ig = g >> 1;
    const int hbase = pi + 8 * ig;    // h_k = hbase + 2k
    const int m0 = mq * 4;

    const int m = m0 + wc;
    int dyk[2];
    bool vk[2];
#pragma unroll
    for (int kk = 0; kk < 2; ++kk) {
        dyk[kk] = m - (2 * kp + kk);
        vk[kk] = (dyk[kk] >= 0) & (dyk[kk] < 21);
    }
    const bool anyv = vk[0] | vk[1];

    const size_t SA = (size_t)(b * 2 + wp) * (64 * 32 * 256);
    const size_t SB = (size_t)(16 + b * 2 + wp) * (64 * 32 * 256);

    // ldmatrix per-lane address components
    const int l7 = lane & 7;
    const int lh = (lane >> 3) & 1;
    const int lq = lane >> 4;
    const uint32_t kxor = l7 << 4;
    const uint32_t khA  = lq * 16;
    const uint32_t khB  = lh * 16;
    uint32_t abase[2][2], bbase[3], bbase6;
#pragma unroll
    for (int kk = 0; kk < 2; ++kk)
#pragma unroll
        for (int mt = 0; mt < 2; ++mt) {
            int row = 32 * (2 * kp + kk) + 16 * mt + l7 + 8 * lh;
            abase[kk][mt] = (row >> 3) * 1024 + l7 * 128;
        }
#pragma unroll
    for (int p = 0; p < 3; ++p) {
        int row = 56 * wc + 16 * p + 8 * lq + l7;
        bbase[p] = (row >> 3) * 1024 + l7 * 128;
    }
    {
        int row = 56 * wc + 48 + l7;
        bbase6 = (row >> 3) * 1024 + l7 * 128;
    }

    float acc[2][2][5][4];             // [kk][mt][window w -> nt = w + 2*mt][reg]
#pragma unroll
    for (int kk = 0; kk < 2; ++kk)
#pragma unroll
        for (int mt = 0; mt < 2; ++mt)
#pragma unroll
            for (int w = 0; w < 5; ++w)
#pragma unroll
                for (int r = 0; r < 4; ++r) acc[kk][mt][w][r] = 0.f;

    // ---- zero entire B regions of both buffers once (pad/OOB rows stay zero)
    {
        float4 zz = make_float4(0.f, 0.f, 0.f, 0.f);
        for (int idx = tid; idx < 2 * 224 * 8; idx += 256) {
            int bi = idx >= 224 * 8;
            int k2 = idx - bi * 224 * 8;
            *(float4*)(smem + bi * BUF + OFF_B + k2 * 16) = zz;
        }
    }

    auto stage = [&](int cc, int bsel) {
        const int c0 = cc * 64;
        const uint32_t bb = sb + bsel * BUF;
        // A: 128 rows x 8 quads = 1024 cp.async over 256 threads
#pragma unroll
        for (int it = 0; it < 4; ++it) {
            int idx = tid + 256 * it;
            int row = idx >> 3, q = idx & 7;
            int k = row >> 5, u = row & 31;
            int h = hbase + 2 * k;
            size_t so = SA + ((size_t)h * 32 + u) * 256 + c0 + q * 8;
            uint32_t dst = (row >> 3) * 1024 + (row & 7) * 128 + ((q * 16) ^ ((row & 7) << 4));
            cp16(bb + OFF_A + dst, g_hi + so);
        }
        // B: 128 valid rows (4 m x 32 xv) x 8 quads; OOB h2 rows stay zero
#pragma unroll
        for (int it = 0; it < 4; ++it) {
            int idx = tid + 256 * it;
            int vr = idx >> 3, q = idx & 7;
            int mloc = vr >> 5, xv = vr & 31;
            int h2 = hbase - 20 + 2 * (m0 + mloc);
            if (h2 >= 0 && h2 < 64) {
                int row = mloc * 56 + xv + 10;
                size_t so = SB + ((size_t)h2 * 32 + xv) * 256 + c0 + q * 8;
                uint32_t dst = (row >> 3) * 1024 + (row & 7) * 128 + ((q * 16) ^ ((row & 7) << 4));
                cp16(bb + OFF_B + dst, g_hi + so);
            }
        }
        asm volatile("cp.async.commit_group;");
    };

    stage(0, 0);

    for (int cc = 0; cc < 4; ++cc) {
        asm volatile("cp.async.wait_group 0;");
        __syncthreads();
        if (cc < 3) stage(cc + 1, (cc + 1) & 1);   // overlaps compute below

        if (anyv) {
            const uint32_t bufb = sb + (cc & 1) * BUF;
            const uint32_t uA = bufb + OFF_A;
            const uint32_t uB = bufb + OFF_B;
#pragma unroll
            for (int s = 0; s < 4; ++s) {
                const uint32_t kb = 32 * s;
                uint32_t bf[7][2];
#pragma unroll
                for (int p = 0; p < 3; ++p)
                    ldsm_x4(bf[2 * p][0], bf[2 * p][1], bf[2 * p + 1][0], bf[2 * p + 1][1],
                            uB + bbase[p] + ((kb + khB) ^ kxor));
                ldsm_x2(bf[6][0], bf[6][1], uB + bbase6 + ((kb + khB) ^ kxor));
#pragma unroll
                for (int kk = 0; kk < 2; ++kk) {
                    if (!vk[kk]) continue;
                    uint32_t ah[2][4];
#pragma unroll
                    for (int mt = 0; mt < 2; ++mt)
                        ldsm_x4(ah[mt][0], ah[mt][1], ah[mt][2], ah[mt][3],
                                uA + abase[kk][mt] + ((kb + khA) ^ kxor));
#pragma unroll
                    for (int mt = 0; mt < 2; ++mt)
#pragma unroll
                        for (int w = 0; w < 5; ++w)
                            mma_f16(acc[kk][mt][w], ah[mt], bf[w + 2 * mt]);
                }
            }
        }
    }
    __syncthreads();   // all compute done before epilogue reuses smem

    // ---- epilogue: per-warp smem [u:32][x] stride 72, STS.64 conflict-free
    float* sD = (float*)(smem + wq * (32 * 72 * 4));
    const float scale = 1.0f / 256.0f;
#pragma unroll
    for (int kk = 0; kk < 2; ++kk) {
        if (!vk[kk]) continue;
#pragma unroll
        for (int mt = 0; mt < 2; ++mt)
#pragma unroll
            for (int w = 0; w < 5; ++w) {
                const int nt = w + 2 * mt;
                const int x0 = 8 * nt + 2 * (lane & 3);
                const int u0 = 16 * mt + (lane >> 2);
                *(float2*)(sD + u0 * 72 + x0)       = make_float2(acc[kk][mt][w][0], acc[kk][mt][w][1]);
                *(float2*)(sD + (u0 + 8) * 72 + x0) = make_float2(acc[kk][mt][w][2], acc[kk][mt][w][3]);
            }
        __syncwarp();

        const int hk = hbase + 2 * (2 * kp + kk);
        size_t ob = ((size_t)b * 441 + (size_t)dyk[kk] * 21) * 4096
                  + (size_t)hk * 64 + wp + 2 * lane;
#pragma unroll
        for (int j = 0; j < 21; ++j)
            out[ob + (size_t)j * 4096] = sD[lane * 72 + lane + j] * scale;
        __syncwarp();
    }
}

} // namespace

extern "C" void kernel_launch(void* const* d_in, const int* in_sizes, int n_in,
                              void* d_out, int out_size)
{
    const float* in1 = (const float*)d_in[0];
    const float* in2 = (const float*)d_in[1];
    float* out = (float*)d_out;

    cudaFuncSetAttribute(corr_mma_kernel,
                         cudaFuncAttributeMaxDynamicSharedMemorySize, SMEM_BYTES);

    dim3 cgrid(8, 64, 16);
    convert_kernel<<<cgrid, 256>>>(in1, in2);

    dim3 grid(6, 16, 16);
    corr_mma_kernel<<<grid, 256, SMEM_BYTES>>>(out);
}